// round 9
// baseline (speedup 1.0000x reference)
#include <cuda_runtime.h>

// SWAttention AV — warp-autonomous pipelines. B=8,H=8,N=3136,D=32,K2=9.
// Block = 128 threads, 16 rows; warp w fully owns rows 4w..4w+3:
// it cp.asyncs its own q+v rows, waits only on ITS groups (per-thread wait_group),
// computes attn and AV for those rows with no block-wide barrier after load issue
// (single early __syncthreads covers the shared lt staging only).

#define HH 8
#define NN 3136
#define NROWS (8 * HH * NN)       // 200704
#define TILE 16
#define NBLOCKS (NROWS / TILE)    // 12544
#define NTHREADS 128

__device__ __forceinline__ unsigned smem_u32(const void* p) {
    return (unsigned)__cvta_generic_to_shared(p);
}
__device__ __forceinline__ void cp16(unsigned dst, const void* src) {
    asm volatile("cp.async.cg.shared.global [%0], [%1], 16;" :: "r"(dst), "l"(src));
}
__device__ __forceinline__ void cp_commit() {
    asm volatile("cp.async.commit_group;");
}

__global__ __launch_bounds__(NTHREADS, 10)
void swattn_kernel(const float* __restrict__ q,
                   const float* __restrict__ attn_local,
                   const float* __restrict__ v,
                   const float* __restrict__ lt,
                   const float* __restrict__ bias,
                   float* __restrict__ out) {
    __shared__ float sq[TILE * 36];    //  2304 B, padded rows, conflict-free f4
    __shared__ float sv[TILE * 288];   // 18432 B, flat; warp w owns [4w*288, +1152)
    __shared__ float sltT[9 * 36];     //  1296 B, lt transposed [k][d], padded
    __shared__ float sa[TILE * 12];    //   768 B, attn tile (warp-private rows)

    const int t    = threadIdx.x;
    const int w    = t >> 5;
    const int lane = t & 31;

    const size_t R0  = (size_t)blockIdx.x * TILE;
    const int    hn0 = (int)(R0 % (HH * NN));
    const int    h   = hn0 / NN;

    const int nl = lane >> 3;          // local row 0..3
    const int k  = lane & 7;
    const int row = (w << 2) + nl;     // tile-local row 0..15

    // ---- Group 0: this warp's q rows (4 x 32 floats = 1 f4/lane, padded dst) ----
    cp16(smem_u32(sq + row * 36 + k * 4), q + R0 * 32 + (w << 7) + lane * 4);
    cp_commit();

    // ---- Group 1: this warp's v rows (4 x 288 floats = 9 f4/lane, contiguous) ----
    {
        const float*   vg = v + (R0 + (w << 2)) * 288;
        const unsigned sd = smem_u32(sv + (w << 2) * 288);
        #pragma unroll
        for (int i = 0; i < 9; i++)
            cp16(sd + (lane + 32 * i) * 16, vg + (lane + 32 * i) * 4);
    }
    cp_commit();

    // ---- Stage lt transposed (shared across warps): sltT[kk][d] = lt[h][d][kk] ----
    #pragma unroll
    for (int i = t; i < 288; i += NTHREADS) {
        const int d = i / 9, kk = i - 9 * d;
        sltT[kk * 36 + d] = lt[h * 288 + i];
    }

    // ---- bias + local into registers (overlaps waits) ----
    const int rk = row * 9 + k;
    float bl  = bias[(size_t)hn0 * 9 + rk] + __ldcs(attn_local + R0 * 9 + rk);
    float bl8 = 0.f;
    if (k == 0)
        bl8 = bias[(size_t)hn0 * 9 + row * 9 + 8] + __ldcs(attn_local + R0 * 9 + row * 9 + 8);

    __syncthreads();                           // sltT visible; loads still streaming

    asm volatile("cp.async.wait_group 1;");    // THIS thread's q copy done
    __syncwarp();                              // whole warp's q rows visible

    // ---- Phase 1: attn for this warp's rows. Lane (nl, k); k==0 also does k=8 ----
    {
        const float4* q4 = reinterpret_cast<const float4*>(sq + row * 36);
        const float4* l4 = reinterpret_cast<const float4*>(sltT + k * 36);
        const float4* l8 = reinterpret_cast<const float4*>(sltT + 8 * 36);
        float acc = bl, acc8 = bl8;
        #pragma unroll
        for (int i = 0; i < 8; i++) {
            const float4 qa = q4[i], lb = l4[i];
            acc = fmaf(qa.x, lb.x, acc);
            acc = fmaf(qa.y, lb.y, acc);
            acc = fmaf(qa.z, lb.z, acc);
            acc = fmaf(qa.w, lb.w, acc);
            if (k == 0) {
                const float4 lc = l8[i];
                acc8 = fmaf(qa.x, lc.x, acc8);
                acc8 = fmaf(qa.y, lc.y, acc8);
                acc8 = fmaf(qa.z, lc.z, acc8);
                acc8 = fmaf(qa.w, lc.w, acc8);
            }
        }
        sa[row * 12 + k] = acc;
        if (k == 0) sa[row * 12 + 8] = acc8;
    }

    asm volatile("cp.async.wait_group 0;");    // THIS thread's v copies done
    __syncwarp();                              // warp's v rows + sa rows visible

    // ---- Phase 2: AV for this warp's rows. Lane: row = 4w + (lane>>3), d-grp = lane&7 ----
    {
        const int g7 = k;                      // lane & 7

        const float* sar = sa + row * 12;
        const float4 A0 = reinterpret_cast<const float4*>(sar)[0];
        const float4 A1 = reinterpret_cast<const float4*>(sar)[1];
        const float a[9] = {A0.x, A0.y, A0.z, A0.w, A1.x, A1.y, A1.z, A1.w, sar[8]};

        // Lane's 36 contiguous floats = v[row][4*g7 .. 4*g7+3][0..8]; static (d,k) decode.
        const float4* wv4 = reinterpret_cast<const float4*>(sv + row * 288 + g7 * 36);
        float acc[4] = {0.f, 0.f, 0.f, 0.f};
        #pragma unroll
        for (int i = 0; i < 9; i++) {
            const float4 wv = wv4[i];
            acc[(4 * i + 0) / 9] = fmaf(a[(4 * i + 0) % 9], wv.x, acc[(4 * i + 0) / 9]);
            acc[(4 * i + 1) / 9] = fmaf(a[(4 * i + 1) % 9], wv.y, acc[(4 * i + 1) / 9]);
            acc[(4 * i + 2) / 9] = fmaf(a[(4 * i + 2) % 9], wv.z, acc[(4 * i + 2) / 9]);
            acc[(4 * i + 3) / 9] = fmaf(a[(4 * i + 3) % 9], wv.w, acc[(4 * i + 3) / 9]);
        }

        const float4 o = make_float4(acc[0], acc[1], acc[2], acc[3]);
        __stcs(reinterpret_cast<float4*>(out + (R0 + row) * 32 + 4 * g7), o);
    }
}

extern "C" void kernel_launch(void* const* d_in, const int* in_sizes, int n_in,
                              void* d_out, int out_size) {
    const float* q          = (const float*)d_in[0];  // [B,H,N,D]
    const float* attn_local = (const float*)d_in[1];  // [B,H,N,K2]
    const float* v_local    = (const float*)d_in[2];  // [B,H,N,D,K2]
    const float* lt         = (const float*)d_in[3];  // [H,D,K2]
    const float* bias       = (const float*)d_in[4];  // [H,N,K2]
    float* out = (float*)d_out;                       // [B,H,N,D]

    swattn_kernel<<<NBLOCKS, NTHREADS>>>(q, attn_local, v_local, lt, bias, out);
}